// round 4
// baseline (speedup 1.0000x reference)
#include <cuda_runtime.h>
#include <cuda_fp16.h>
#include <cstdint>

#define NB 16
#define NS 256
#define ND 512
#define NH 512
#define NG 2048
#define LN_EPS 1e-5f

// ---------------------------------------------------------------------------
// Static device scratch (allocation-free rule): ~100 MB total.
// Packed fp16 weights: layout [b*4+gate][kc=0..63][a=0..1][t=0..255] of uint4
// (8 halves of row (gate*512 + a*256 + t), k-chunk kc).
// ---------------------------------------------------------------------------
__device__ uint4  g_whh0p[NB * NG * NH / 8];   // 33.5 MB
__device__ uint4  g_w1p  [NB * NG * NH / 8];   // 33.5 MB  (wih1 + whh1)
__device__ float4 g_gih4 [NB * NS * NG / 4];   // 33.5 MB  (wih0@x + bih0 + bhh0)

// ---------------------------------------------------------------------------
__device__ __forceinline__ float2 h2_to_f2(unsigned u) {
    __half2 h = *reinterpret_cast<__half2*>(&u);
    return __half22float2(h);
}
__device__ __forceinline__ float sigmoid_f(float x) {
    return 1.0f / (1.0f + __expf(-x));
}
__device__ __forceinline__ void cluster_sync_() {
    asm volatile("barrier.cluster.arrive.aligned;\n\t"
                 "barrier.cluster.wait.aligned;" ::: "memory");
}
__device__ __forceinline__ float ds_read(uint32_t addr, uint32_t rank) {
    uint32_t ra; float v;
    asm volatile("mapa.shared::cluster.u32 %0, %1, %2;" : "=r"(ra) : "r"(addr), "r"(rank));
    asm volatile("ld.shared::cluster.f32 %0, [%1];" : "=f"(v) : "r"(ra) : "memory");
    return v;
}
__device__ __forceinline__ float dot8(uint4 w, float4 ha, float4 hb, float acc) {
    float2 p;
    p = h2_to_f2(w.x); acc = fmaf(p.x, ha.x, acc); acc = fmaf(p.y, ha.y, acc);
    p = h2_to_f2(w.y); acc = fmaf(p.x, ha.z, acc); acc = fmaf(p.y, ha.w, acc);
    p = h2_to_f2(w.z); acc = fmaf(p.x, hb.x, acc); acc = fmaf(p.y, hb.y, acc);
    p = h2_to_f2(w.w); acc = fmaf(p.x, hb.z, acc); acc = fmaf(p.y, hb.w, acc);
    return acc;
}

// Deterministic block reduction for LayerNorm stats over 512 values
// (2 per thread, 256 threads). Identical result in every CTA of a cluster.
__device__ __forceinline__ void block_stats(float v0, float v1, float* red,
                                            float* mean, float* rstd) {
    float s = v0 + v1;
    float q = v0 * v0 + v1 * v1;
    #pragma unroll
    for (int o = 16; o > 0; o >>= 1) {
        s += __shfl_xor_sync(0xffffffffu, s, o);
        q += __shfl_xor_sync(0xffffffffu, q, o);
    }
    __syncthreads();                      // protect red from previous use
    int w = threadIdx.x >> 5;
    if ((threadIdx.x & 31) == 0) { red[w] = s; red[8 + w] = q; }
    __syncthreads();
    s = 0.f; q = 0.f;
    #pragma unroll
    for (int i = 0; i < 8; i++) { s += red[i]; q += red[8 + i]; }
    float m = s * (1.0f / 512.0f);
    float v = q * (1.0f / 512.0f) - m * m;
    *mean = m;
    *rstd = rsqrtf(v + LN_EPS);
}

// ---------------------------------------------------------------------------
// Kernel 1: pack whh0 and (wih1+whh1) to fp16 in coalesced layout.
// ---------------------------------------------------------------------------
__global__ void __launch_bounds__(256) pack_kernel(const float* __restrict__ whh0,
                                                   const float* __restrict__ wih1,
                                                   const float* __restrict__ whh1) {
    int idx = blockIdx.x * 256 + threadIdx.x;       // 0 .. 2097151
    int t  = idx & 255;
    int a  = (idx >> 8) & 1;
    int kc = (idx >> 9) & 63;
    int bg = idx >> 15;                             // b*4 + gate
    int row = (bg & 3) * 512 + a * 256 + t;
    int b   = bg >> 2;
    long src = ((long)b * NG + row) * NH + (long)kc * 8;

    const float* s0 = whh0 + src;
    const float* s1 = wih1 + src;
    const float* s2 = whh1 + src;
    __half2 p; uint4 o0, o1;
    p = __floats2half2_rn(s0[0], s0[1]);             o0.x = *reinterpret_cast<unsigned*>(&p);
    p = __floats2half2_rn(s0[2], s0[3]);             o0.y = *reinterpret_cast<unsigned*>(&p);
    p = __floats2half2_rn(s0[4], s0[5]);             o0.z = *reinterpret_cast<unsigned*>(&p);
    p = __floats2half2_rn(s0[6], s0[7]);             o0.w = *reinterpret_cast<unsigned*>(&p);
    p = __floats2half2_rn(s1[0]+s2[0], s1[1]+s2[1]); o1.x = *reinterpret_cast<unsigned*>(&p);
    p = __floats2half2_rn(s1[2]+s2[2], s1[3]+s2[3]); o1.y = *reinterpret_cast<unsigned*>(&p);
    p = __floats2half2_rn(s1[4]+s2[4], s1[5]+s2[5]); o1.z = *reinterpret_cast<unsigned*>(&p);
    p = __floats2half2_rn(s1[6]+s2[6], s1[7]+s2[7]); o1.w = *reinterpret_cast<unsigned*>(&p);
    g_whh0p[idx] = o0;
    g_w1p[idx]   = o1;
}

// ---------------------------------------------------------------------------
// Kernel 2: GIH0[b][t][row] = wih0[b] @ x[b,t] + bih0 + bhh0  (fp32).
// grid (32 row-tiles, 4 t-tiles, 16 b), 256 thr, 64x64 tile, BK=16, 4x4/thread.
// ---------------------------------------------------------------------------
__global__ void __launch_bounds__(256) gih_gemm(const float* __restrict__ wih0,
                                                const float* __restrict__ x,
                                                const float* __restrict__ bih0,
                                                const float* __restrict__ bhh0) {
    __shared__ float As[16][68];   // [k][row]
    __shared__ float Bs[16][68];   // [k][t]
    const int b    = blockIdx.z;
    const int row0 = blockIdx.x * 64;
    const int t0   = blockIdx.y * 64;
    const int tid  = threadIdx.x;
    const int tx   = tid & 15;     // row group
    const int ty   = tid >> 4;     // t group
    const int lr   = tid >> 2;     // 0..63 load row
    const int ld   = (tid & 3) * 4;

    const float* Ag = wih0 + ((long)b * NG + row0 + lr) * ND + ld;
    const float* Bg = x    + ((long)b * NS + t0   + lr) * ND + ld;

    float acc[4][4];
    #pragma unroll
    for (int i = 0; i < 4; i++)
        #pragma unroll
        for (int j = 0; j < 4; j++) acc[i][j] = 0.f;

    for (int d0 = 0; d0 < ND; d0 += 16) {
        float4 av = *reinterpret_cast<const float4*>(Ag + d0);
        float4 bv = *reinterpret_cast<const float4*>(Bg + d0);
        __syncthreads();
        As[ld+0][lr] = av.x; As[ld+1][lr] = av.y; As[ld+2][lr] = av.z; As[ld+3][lr] = av.w;
        Bs[ld+0][lr] = bv.x; Bs[ld+1][lr] = bv.y; Bs[ld+2][lr] = bv.z; Bs[ld+3][lr] = bv.w;
        __syncthreads();
        #pragma unroll
        for (int kk = 0; kk < 16; kk++) {
            float a4[4], b4[4];
            *reinterpret_cast<float4*>(a4) = *reinterpret_cast<const float4*>(&As[kk][tx * 4]);
            *reinterpret_cast<float4*>(b4) = *reinterpret_cast<const float4*>(&Bs[kk][ty * 4]);
            #pragma unroll
            for (int i = 0; i < 4; i++)
                #pragma unroll
                for (int j = 0; j < 4; j++)
                    acc[i][j] = fmaf(a4[j], b4[i], acc[i][j]);
        }
    }
    int rr = row0 + tx * 4;
    float bb[4];
    #pragma unroll
    for (int j = 0; j < 4; j++) bb[j] = bih0[b * NG + rr + j] + bhh0[b * NG + rr + j];
    #pragma unroll
    for (int i = 0; i < 4; i++) {
        int t = t0 + ty * 4 + i;
        float4 o;
        o.x = acc[i][0] + bb[0];
        o.y = acc[i][1] + bb[1];
        o.z = acc[i][2] + bb[2];
        o.w = acc[i][3] + bb[3];
        g_gih4[((long)b * NS + t) * 512 + (rr >> 2)] = o;
    }
}

// ---------------------------------------------------------------------------
// Kernel 3: persistent recurrent LSTM. 16 clusters x 4 CTAs (one per gate),
// 256 threads. Thread handles gate positions tid and tid+256.
// ---------------------------------------------------------------------------
__device__ __forceinline__ void matvec2(const uint4* __restrict__ wp,
                                        const float* __restrict__ hh,
                                        float& acc0, float& acc1) {
    #pragma unroll 8
    for (int kc = 0; kc < 64; kc++) {
        float4 ha = *reinterpret_cast<const float4*>(hh + kc * 8);
        float4 hb = *reinterpret_cast<const float4*>(hh + kc * 8 + 4);
        uint4 w0 = wp[kc * 512];
        uint4 w1 = wp[kc * 512 + 256];
        acc0 = dot8(w0, ha, hb, acc0);
        acc1 = dot8(w1, ha, hb, acc1);
    }
}

__global__ void __cluster_dims__(4, 1, 1) __launch_bounds__(256, 1)
lstm_rec(const float* __restrict__ bih1, const float* __restrict__ bhh1,
         const float* __restrict__ ln_w, const float* __restrict__ ln_b,
         float* __restrict__ out) {
    __shared__ float sh_h[512];
    __shared__ float sh_act[2][512];
    __shared__ float sh_red[16];

    const int tid  = threadIdx.x;
    const int bg   = blockIdx.x;       // 0..63
    const int b    = bg >> 2;
    const int gate = bg & 3;           // == cluster rank

    // constants per thread
    const float gw0a = ln_w[tid],       gw0b = ln_w[tid + 256];
    const float gb0a = ln_b[tid],       gb0b = ln_b[tid + 256];
    const float gw1a = ln_w[512 + tid], gw1b = ln_w[512 + tid + 256];
    const float gb1a = ln_b[512 + tid], gb1b = ln_b[512 + tid + 256];
    const long  brow = (long)b * NG + gate * 512;
    const float bias1a = bih1[brow + tid]       + bhh1[brow + tid];
    const float bias1b = bih1[brow + tid + 256] + bhh1[brow + tid + 256];

    const uint4* w0p = g_whh0p + (size_t)bg * (64 * 512) + tid;
    const uint4* w1p = g_w1p   + (size_t)bg * (64 * 512) + tid;
    const float* gih = reinterpret_cast<const float*>(g_gih4)
                       + (size_t)b * NS * NG + gate * 512 + tid;

    const uint32_t act0a = (uint32_t)__cvta_generic_to_shared(&sh_act[0][tid]);
    const uint32_t act0b = (uint32_t)__cvta_generic_to_shared(&sh_act[0][tid + 256]);
    const uint32_t act1a = (uint32_t)__cvta_generic_to_shared(&sh_act[1][tid]);
    const uint32_t act1b = (uint32_t)__cvta_generic_to_shared(&sh_act[1][tid + 256]);

    sh_h[tid] = 0.f; sh_h[tid + 256] = 0.f;
    float c0 = 0.f, c1 = 0.f;
    __syncthreads();

    for (int t = 0; t < NS; t++) {
        // ================= layer 0 =================
        float acc0 = gih[(size_t)t * NG];
        float acc1 = gih[(size_t)t * NG + 256];
        matvec2(w0p, sh_h, acc0, acc1);

        float m, rs;
        block_stats(acc0, acc1, sh_red, &m, &rs);
        float n0 = (acc0 - m) * rs * gw0a + gb0a;
        float n1 = (acc1 - m) * rs * gw0b + gb0b;
        float v0 = (gate == 2) ? tanhf(n0) : sigmoid_f(n0);
        float v1 = (gate == 2) ? tanhf(n1) : sigmoid_f(n1);
        sh_act[0][tid] = v0; sh_act[0][tid + 256] = v1;
        cluster_sync_();

        float iv0 = ds_read(act0a, 0), fv0 = ds_read(act0a, 1);
        float gv0 = ds_read(act0a, 2), ov0 = ds_read(act0a, 3);
        float iv1 = ds_read(act0b, 0), fv1 = ds_read(act0b, 1);
        float gv1 = ds_read(act0b, 2), ov1 = ds_read(act0b, 3);
        c0 = fmaf(fv0, c0, iv0 * gv0);
        c1 = fmaf(fv1, c1, iv1 * gv1);

        block_stats(c0, c1, sh_red, &m, &rs);
        float h0 = ov0 * tanhf((c0 - m) * rs * gw0a + gb0a);
        float h1 = ov1 * tanhf((c1 - m) * rs * gw0b + gb0b);
        sh_h[tid] = h0; sh_h[tid + 256] = h1;
        __syncthreads();

        // ================= layer 1 =================
        acc0 = bias1a; acc1 = bias1b;
        matvec2(w1p, sh_h, acc0, acc1);

        block_stats(acc0, acc1, sh_red, &m, &rs);
        n0 = (acc0 - m) * rs * gw1a + gb1a;
        n1 = (acc1 - m) * rs * gw1b + gb1b;
        v0 = (gate == 2) ? tanhf(n0) : sigmoid_f(n0);
        v1 = (gate == 2) ? tanhf(n1) : sigmoid_f(n1);
        sh_act[1][tid] = v0; sh_act[1][tid + 256] = v1;
        cluster_sync_();

        iv0 = ds_read(act1a, 0); fv0 = ds_read(act1a, 1);
        gv0 = ds_read(act1a, 2); ov0 = ds_read(act1a, 3);
        iv1 = ds_read(act1b, 0); fv1 = ds_read(act1b, 1);
        gv1 = ds_read(act1b, 2); ov1 = ds_read(act1b, 3);
        c0 = fmaf(fv0, c0, iv0 * gv0);
        c1 = fmaf(fv1, c1, iv1 * gv1);

        block_stats(c0, c1, sh_red, &m, &rs);
        h0 = ov0 * tanhf((c0 - m) * rs * gw1a + gb1a);
        h1 = ov1 * tanhf((c1 - m) * rs * gw1b + gb1b);
        sh_h[tid] = h0; sh_h[tid + 256] = h1;
        __syncthreads();

        // output (redundant across the 4 CTAs — identical deterministic values)
        float* op = out + ((size_t)b * NS + t) * NH;
        op[tid] = h0;
        op[tid + 256] = h1;
    }
}

// ---------------------------------------------------------------------------
extern "C" void kernel_launch(void* const* d_in, const int* in_sizes, int n_in,
                              void* d_out, int out_size) {
    const float* x    = (const float*)d_in[0];
    const float* wih0 = (const float*)d_in[1];
    const float* whh0 = (const float*)d_in[2];
    const float* bih0 = (const float*)d_in[3];
    const float* bhh0 = (const float*)d_in[4];
    const float* wih1 = (const float*)d_in[5];
    const float* whh1 = (const float*)d_in[6];
    const float* bih1 = (const float*)d_in[7];
    const float* bhh1 = (const float*)d_in[8];
    const float* ln_w = (const float*)d_in[9];
    const float* ln_b = (const float*)d_in[10];
    float* out = (float*)d_out;

    pack_kernel<<<NB * NG * NH / 8 / 256, 256>>>(whh0, wih1, whh1);
    dim3 gg(NG / 64, NS / 64, NB);
    gih_gemm<<<gg, 256>>>(wih0, x, bih0, bhh0);
    lstm_rec<<<NB * 4, 256>>>(bih1, bhh1, ln_w, ln_b, out);
}

// round 6
// speedup vs baseline: 1.0713x; 1.0713x over previous
#include <cuda_runtime.h>
#include <cuda_fp16.h>
#include <cstdint>

#define NB 16
#define NS 256
#define ND 512
#define NH 512
#define NG 2048
#define LN_EPS 1e-5f

// ---------------------------------------------------------------------------
// Static device scratch (allocation-free rule): ~100 MB total.
// Packed fp16 weights: [b*4+gate][kh=0..1][kc'=0..31][a=0..1][t=0..255] uint4
// = 8 halves of row (gate*512 + a*256 + t), k-range kh*256 + kc'*8 .. +7.
// ---------------------------------------------------------------------------
__device__ uint4  g_whh0p[NB * NG * NH / 8];   // 33.5 MB
__device__ uint4  g_w1p  [NB * NG * NH / 8];   // 33.5 MB  (wih1 + whh1)
__device__ float4 g_gih4 [NB * NS * NG / 4];   // 33.5 MB  (wih0@x + bih0 + bhh0)

// ---------------------------------------------------------------------------
__device__ __forceinline__ float2 h2_to_f2(unsigned u) {
    __half2 h = *reinterpret_cast<__half2*>(&u);
    return __half22float2(h);
}
__device__ __forceinline__ float sigmoid_f(float x) {
    return 1.0f / (1.0f + __expf(-x));
}
__device__ __forceinline__ void cluster_sync_() {
    asm volatile("barrier.cluster.arrive.aligned;\n\t"
                 "barrier.cluster.wait.aligned;" ::: "memory");
}
__device__ __forceinline__ float ds_read(uint32_t addr, uint32_t rank) {
    uint32_t ra; float v;
    asm volatile("mapa.shared::cluster.u32 %0, %1, %2;" : "=r"(ra) : "r"(addr), "r"(rank));
    asm volatile("ld.shared::cluster.f32 %0, [%1];" : "=f"(v) : "r"(ra) : "memory");
    return v;
}
__device__ __forceinline__ float dot8(uint4 w, float4 ha, float4 hb, float acc) {
    float2 p;
    p = h2_to_f2(w.x); acc = fmaf(p.x, ha.x, acc); acc = fmaf(p.y, ha.y, acc);
    p = h2_to_f2(w.y); acc = fmaf(p.x, ha.z, acc); acc = fmaf(p.y, ha.w, acc);
    p = h2_to_f2(w.z); acc = fmaf(p.x, hb.x, acc); acc = fmaf(p.y, hb.y, acc);
    p = h2_to_f2(w.w); acc = fmaf(p.x, hb.z, acc); acc = fmaf(p.y, hb.w, acc);
    return acc;
}

// Deterministic LayerNorm stats over 512 local values (2/thread, 256 thr).
__device__ __forceinline__ void block_stats(float v0, float v1, float* red,
                                            float* mean, float* rstd) {
    float s = v0 + v1;
    float q = v0 * v0 + v1 * v1;
    #pragma unroll
    for (int o = 16; o > 0; o >>= 1) {
        s += __shfl_xor_sync(0xffffffffu, s, o);
        q += __shfl_xor_sync(0xffffffffu, q, o);
    }
    __syncthreads();
    int w = threadIdx.x >> 5;
    if ((threadIdx.x & 31) == 0) { red[w] = s; red[8 + w] = q; }
    __syncthreads();
    s = 0.f; q = 0.f;
    #pragma unroll
    for (int i = 0; i < 8; i++) { s += red[i]; q += red[8 + i]; }
    float m = s * (1.0f / 512.0f);
    float v = q * (1.0f / 512.0f) - m * m;
    *mean = m;
    *rstd = rsqrtf(v + LN_EPS);
}

// ---------------------------------------------------------------------------
// Kernel 1: pack whh0 and (wih1+whh1) to fp16. COALESCED READS (3x volume of
// writes): thread n reads 8 consecutive floats from each source array.
// ---------------------------------------------------------------------------
__global__ void __launch_bounds__(256) pack_kernel(const float* __restrict__ whh0,
                                                   const float* __restrict__ wih1,
                                                   const float* __restrict__ whh1) {
    int n = blockIdx.x * 256 + threadIdx.x;          // 0 .. 2097151
    int kc  = n & 63;
    int row = (n >> 6) & 2047;
    int b   = n >> 17;
    long src = ((long)(b * 2048 + row)) * 512 + (long)kc * 8;

    int gate = row >> 9, a = (row >> 8) & 1, t = row & 255;
    int kh = kc >> 5, kcp = kc & 31;
    int dst = (((b * 4 + gate) * 2 + kh) * 32 + kcp) * 512 + a * 256 + t;

    const float* s0 = whh0 + src;
    const float* s1 = wih1 + src;
    const float* s2 = whh1 + src;
    __half2 p; uint4 o0, o1;
    p = __floats2half2_rn(s0[0], s0[1]);             o0.x = *reinterpret_cast<unsigned*>(&p);
    p = __floats2half2_rn(s0[2], s0[3]);             o0.y = *reinterpret_cast<unsigned*>(&p);
    p = __floats2half2_rn(s0[4], s0[5]);             o0.z = *reinterpret_cast<unsigned*>(&p);
    p = __floats2half2_rn(s0[6], s0[7]);             o0.w = *reinterpret_cast<unsigned*>(&p);
    p = __floats2half2_rn(s1[0]+s2[0], s1[1]+s2[1]); o1.x = *reinterpret_cast<unsigned*>(&p);
    p = __floats2half2_rn(s1[2]+s2[2], s1[3]+s2[3]); o1.y = *reinterpret_cast<unsigned*>(&p);
    p = __floats2half2_rn(s1[4]+s2[4], s1[5]+s2[5]); o1.z = *reinterpret_cast<unsigned*>(&p);
    p = __floats2half2_rn(s1[6]+s2[6], s1[7]+s2[7]); o1.w = *reinterpret_cast<unsigned*>(&p);
    g_whh0p[dst] = o0;
    g_w1p[dst]   = o1;
}

// ---------------------------------------------------------------------------
// Kernel 2: GIH0[b][t][row] = wih0[b] @ x[b,t] + bih0 + bhh0  (fp32).
// ---------------------------------------------------------------------------
__global__ void __launch_bounds__(256) gih_gemm(const float* __restrict__ wih0,
                                                const float* __restrict__ x,
                                                const float* __restrict__ bih0,
                                                const float* __restrict__ bhh0) {
    __shared__ float As[16][68];
    __shared__ float Bs[16][68];
    const int b    = blockIdx.z;
    const int row0 = blockIdx.x * 64;
    const int t0   = blockIdx.y * 64;
    const int tid  = threadIdx.x;
    const int tx   = tid & 15;
    const int ty   = tid >> 4;
    const int lr   = tid >> 2;
    const int ld   = (tid & 3) * 4;

    const float* Ag = wih0 + ((long)b * NG + row0 + lr) * ND + ld;
    const float* Bg = x    + ((long)b * NS + t0   + lr) * ND + ld;

    float acc[4][4];
    #pragma unroll
    for (int i = 0; i < 4; i++)
        #pragma unroll
        for (int j = 0; j < 4; j++) acc[i][j] = 0.f;

    for (int d0 = 0; d0 < ND; d0 += 16) {
        float4 av = *reinterpret_cast<const float4*>(Ag + d0);
        float4 bv = *reinterpret_cast<const float4*>(Bg + d0);
        __syncthreads();
        As[ld+0][lr] = av.x; As[ld+1][lr] = av.y; As[ld+2][lr] = av.z; As[ld+3][lr] = av.w;
        Bs[ld+0][lr] = bv.x; Bs[ld+1][lr] = bv.y; Bs[ld+2][lr] = bv.z; Bs[ld+3][lr] = bv.w;
        __syncthreads();
        #pragma unroll
        for (int kk = 0; kk < 16; kk++) {
            float a4[4], b4[4];
            *reinterpret_cast<float4*>(a4) = *reinterpret_cast<const float4*>(&As[kk][tx * 4]);
            *reinterpret_cast<float4*>(b4) = *reinterpret_cast<const float4*>(&Bs[kk][ty * 4]);
            #pragma unroll
            for (int i = 0; i < 4; i++)
                #pragma unroll
                for (int j = 0; j < 4; j++)
                    acc[i][j] = fmaf(a4[j], b4[i], acc[i][j]);
        }
    }
    int rr = row0 + tx * 4;
    float bb[4];
    #pragma unroll
    for (int j = 0; j < 4; j++) bb[j] = bih0[b * NG + rr + j] + bhh0[b * NG + rr + j];
    #pragma unroll
    for (int i = 0; i < 4; i++) {
        int t = t0 + ty * 4 + i;
        float4 o;
        o.x = acc[i][0] + bb[0];
        o.y = acc[i][1] + bb[1];
        o.z = acc[i][2] + bb[2];
        o.w = acc[i][3] + bb[3];
        g_gih4[((long)b * NS + t) * 512 + (rr >> 2)] = o;
    }
}

// ---------------------------------------------------------------------------
// Kernel 3: recurrent LSTM. 16 clusters x 8 CTAs: rank = gate*2 + khalf.
// Each CTA computes partial dots for all 512 rows of its gate over half the
// k-range; sibling pairs (rank^1) exchange partials (commutative add ->
// bitwise-identical full pre-activations in both). LN stats, acts, c, h are
// then computed fully redundantly per CTA (deterministic), so no h exchange.
// ---------------------------------------------------------------------------
__device__ __forceinline__ void matvec_half(const uint4* __restrict__ wp,
                                            const float* __restrict__ hh,
                                            float& acc0, float& acc1) {
    #pragma unroll 8
    for (int kc = 0; kc < 32; kc++) {
        float4 ha = *reinterpret_cast<const float4*>(hh + kc * 8);
        float4 hb = *reinterpret_cast<const float4*>(hh + kc * 8 + 4);
        uint4 w0 = wp[kc * 512];
        uint4 w1 = wp[kc * 512 + 256];
        acc0 = dot8(w0, ha, hb, acc0);
        acc1 = dot8(w1, ha, hb, acc1);
    }
}

__global__ void __cluster_dims__(8, 1, 1) __launch_bounds__(256, 1)
lstm_rec(const float* __restrict__ bih1, const float* __restrict__ bhh1,
         const float* __restrict__ ln_w, const float* __restrict__ ln_b,
         float* __restrict__ out) {
    __shared__ float sh_h[512];
    __shared__ float sh_part[512];
    __shared__ float sh_act[512];
    __shared__ float sh_red[16];

    const int tid  = threadIdx.x;
    const int b    = blockIdx.x >> 3;
    const int rank = blockIdx.x & 7;
    const int gate = rank >> 1;
    const int half = rank & 1;
    const int bg   = b * 4 + gate;

    // per-thread constants
    const float gw0a = ln_w[tid],       gw0b = ln_w[tid + 256];
    const float gb0a = ln_b[tid],       gb0b = ln_b[tid + 256];
    const float gw1a = ln_w[512 + tid], gw1b = ln_w[512 + tid + 256];
    const float gb1a = ln_b[512 + tid], gb1b = ln_b[512 + tid + 256];
    const long  brow = (long)b * NG + gate * 512;
    // bias for layer 1: added exactly once per row across the sibling pair
    const float bias1a = half ? 0.f : (bih1[brow + tid]       + bhh1[brow + tid]);
    const float bias1b = half ? (bih1[brow + tid + 256] + bhh1[brow + tid + 256]) : 0.f;

    const uint4* w0p = g_whh0p + ((size_t)(bg * 2 + half)) * 16384 + tid;
    const uint4* w1p = g_w1p   + ((size_t)(bg * 2 + half)) * 16384 + tid;
    // gih for layer 0: half 0 contributes row tid, half 1 contributes row tid+256
    const float* gihp = reinterpret_cast<const float*>(g_gih4)
                        + (size_t)b * NS * NG + gate * 512 + (half ? tid + 256 : tid);

    const uint32_t part_a = (uint32_t)__cvta_generic_to_shared(&sh_part[tid]);
    const uint32_t part_b = (uint32_t)__cvta_generic_to_shared(&sh_part[tid + 256]);
    const uint32_t act_a  = (uint32_t)__cvta_generic_to_shared(&sh_act[tid]);
    const uint32_t act_b  = (uint32_t)__cvta_generic_to_shared(&sh_act[tid + 256]);
    const uint32_t r_i = gate ^ 0 ? (0 * 2 + half) : (0 * 2 + half); // rank of gate g sibling with same parity
    const uint32_t ri = 0 * 2 + half, rf = 1 * 2 + half, rg = 2 * 2 + half, ro = 3 * 2 + half;
    (void)r_i;

    const float* hh = sh_h + half * 256;    // this CTA's k-range of h

    sh_h[tid] = 0.f; sh_h[tid + 256] = 0.f;
    float c0 = 0.f, c1 = 0.f;
    __syncthreads();

    for (int t = 0; t < NS; t++) {
        #pragma unroll
        for (int layer = 0; layer < 2; layer++) {
            const float gwa = layer ? gw1a : gw0a, gwb = layer ? gw1b : gw0b;
            const float gba = layer ? gb1a : gb0a, gbb = layer ? gb1b : gb0b;

            // partial matvec over this CTA's k-half
            float acc0, acc1;
            if (layer == 0) {
                acc0 = half ? 0.f : gihp[(size_t)t * NG];
                acc1 = half ? gihp[(size_t)t * NG] : 0.f;
                matvec_half(w0p, hh, acc0, acc1);
            } else {
                acc0 = bias1a; acc1 = bias1b;
                matvec_half(w1p, hh, acc0, acc1);
            }

            // exchange partials with sibling (rank^1)
            sh_part[tid] = acc0; sh_part[tid + 256] = acc1;
            cluster_sync_();
            acc0 += ds_read(part_a, rank ^ 1);
            acc1 += ds_read(part_b, rank ^ 1);

            // gate LayerNorm + activation (full 512 values local now)
            float m, rs;
            block_stats(acc0, acc1, sh_red, &m, &rs);
            float n0 = (acc0 - m) * rs * gwa + gba;
            float n1 = (acc1 - m) * rs * gwb + gbb;
            float v0 = (gate == 2) ? tanhf(n0) : sigmoid_f(n0);
            float v1 = (gate == 2) ? tanhf(n1) : sigmoid_f(n1);
            sh_act[tid] = v0; sh_act[tid + 256] = v1;
            cluster_sync_();

            // gather i,f,g,o (read from the same-parity CTA of each gate)
            float iv0 = ds_read(act_a, ri), fv0 = ds_read(act_a, rf);
            float gv0 = ds_read(act_a, rg), ov0 = ds_read(act_a, ro);
            float iv1 = ds_read(act_b, ri), fv1 = ds_read(act_b, rf);
            float gv1 = ds_read(act_b, rg), ov1 = ds_read(act_b, ro);
            c0 = fmaf(fv0, c0, iv0 * gv0);
            c1 = fmaf(fv1, c1, iv1 * gv1);

            // cell LayerNorm -> h (redundant + deterministic in every CTA)
            block_stats(c0, c1, sh_red, &m, &rs);
            float h0 = ov0 * tanhf((c0 - m) * rs * gwa + gba);
            float h1 = ov1 * tanhf((c1 - m) * rs * gwb + gbb);
            sh_h[tid] = h0; sh_h[tid + 256] = h1;
            __syncthreads();

            if (layer == 1 && rank == 0) {
                float* op = out + ((size_t)b * NS + t) * NH;
                op[tid] = h0;
                op[tid + 256] = h1;
            }
        }
    }
}

// ---------------------------------------------------------------------------
extern "C" void kernel_launch(void* const* d_in, const int* in_sizes, int n_in,
                              void* d_out, int out_size) {
    const float* x    = (const float*)d_in[0];
    const float* wih0 = (const float*)d_in[1];
    const float* whh0 = (const float*)d_in[2];
    const float* bih0 = (const float*)d_in[3];
    const float* bhh0 = (const float*)d_in[4];
    const float* wih1 = (const float*)d_in[5];
    const float* whh1 = (const float*)d_in[6];
    const float* bih1 = (const float*)d_in[7];
    const float* bhh1 = (const float*)d_in[8];
    const float* ln_w = (const float*)d_in[9];
    const float* ln_b = (const float*)d_in[10];
    float* out = (float*)d_out;

    pack_kernel<<<NB * NG * NH / 8 / 256, 256>>>(whh0, wih1, whh1);
    dim3 gg(NG / 64, NS / 64, NB);
    gih_gemm<<<gg, 256>>>(wih0, x, bih0, bhh0);
    lstm_rec<<<NB * 8, 256>>>(bih1, bhh1, ln_w, ln_b, out);
}